// round 13
// baseline (speedup 1.0000x reference)
#include <cuda_runtime.h>
#include <math.h>
#include <stdint.h>

#define FULLMASK 0xffffffffu

constexpr int Bb = 8;
constexpr int Nn = 7168;
constexpr int Uu = 49152;
constexpr int Cc = 64;

// scratch buffers
__device__ float g_z1[Bb * Nn * Cc];     // post-LN1 attention output
__device__ float gM[64 * 264];           // folded W-projection matrix (tf32 values)
__device__ float gC[264];                // folded bias row
__device__ float gWv[256 * 72];          // block-diagonal V matrix (tf32), row=g*64+in

__device__ __forceinline__ float to_tf32(float x) {
    uint32_t r;
    asm("cvt.rna.tf32.f32 %0, %1;" : "=r"(r) : "f"(x));
    return __uint_as_float(r);
}

__device__ __forceinline__ void mma_tf32(float c[4],
    uint32_t a0, uint32_t a1, uint32_t a2, uint32_t a3,
    uint32_t b0, uint32_t b1)
{
    asm volatile(
        "mma.sync.aligned.m16n8k8.row.col.f32.tf32.tf32.f32 "
        "{%0,%1,%2,%3},{%4,%5,%6,%7},{%8,%9},{%0,%1,%2,%3};\n"
        : "+f"(c[0]), "+f"(c[1]), "+f"(c[2]), "+f"(c[3])
        : "r"(a0), "r"(a1), "r"(a2), "r"(a3), "r"(b0), "r"(b1));
}

// ---------------------------------------------------------------------------
// Kernel M: fold Wq/Wk/bq/bk (+scale) into gM/gC; build block-diagonal gWv
// ---------------------------------------------------------------------------
extern "C" __global__ void kernelM(
    const float* __restrict__ Wk, const float* __restrict__ bk,
    const float* __restrict__ Wq, const float* __restrict__ bq,
    const float* __restrict__ Wv)
{
    int idx = blockIdx.x * 256 + threadIdx.x;
    if (idx < 64 * 264) {
        int j = idx / 264, col = idx % 264;
        float acc = 0.f;
        if (col < 256) {
            int g = col >> 6, in = col & 63;
#pragma unroll
            for (int oo = 0; oo < 16; oo++) {
                int oc = g * 16 + oo;
                acc += Wq[j * 64 + oc] * Wk[in * 64 + oc];
            }
        } else if (col < 260) {
            int g = col - 256;
#pragma unroll
            for (int oo = 0; oo < 16; oo++) {
                int oc = g * 16 + oo;
                acc += Wq[j * 64 + oc] * bk[oc];
            }
        }
        gM[idx] = to_tf32(0.125f * acc);
    } else if (idx < 64 * 264 + 264) {
        int col = idx - 64 * 264;
        float acc = 0.f;
        if (col < 256) {
            int g = col >> 6, in = col & 63;
#pragma unroll
            for (int oo = 0; oo < 16; oo++) {
                int oc = g * 16 + oo;
                acc += bq[oc] * Wk[in * 64 + oc];
            }
        } else if (col < 260) {
            int g = col - 256;
#pragma unroll
            for (int oo = 0; oo < 16; oo++) {
                int oc = g * 16 + oo;
                acc += bq[oc] * bk[oc];
            }
        }
        gC[col] = 0.125f * acc;
    } else if (idx < 64 * 264 + 264 + 256 * 72) {
        int j = idx - (64 * 264 + 264);
        int row = j / 72, oc = j % 72;
        float v = 0.f;
        if (oc < 64) {
            int g = row >> 6, in = row & 63;
            if ((oc >> 4) == g) v = Wv[in * 64 + oc];
        }
        gWv[row * 72 + oc] = to_tf32(v);
    }
}

// ---------------------------------------------------------------------------
// Kernel A attention epilogue for one token: logits/softmax/ubar -> sWt row
// ---------------------------------------------------------------------------
template <int TO>
__device__ __forceinline__ void attn_tok(
    const float* __restrict__ u,
    float* sWt, float* myLog, int b, int n, int ltok, int l)
{
    int t, S0, S1;
    if (TO == 4)      { t = n;        S0 = 0;     S1 = 24576; }
    else if (TO == 8) { t = n - 4096; S0 = 8192;  S1 = 32768; }
    else              { t = n - 6144; S0 = 16384; S1 = 40960; }
    int cidx = t * TO;
    int base = (cidx < 8192) ? (S0 + cidx) : (S1 + cidx - 8192);
    const float* uptr = u + ((size_t)b * Uu + base) * Cc;

    float* wrow = sWt + ltok * 265;
    float wg0[4], wg1[4];
#pragma unroll
    for (int g = 0; g < 4; g++) {
        wg0[g] = wrow[g * 64 + l];
        wg1[g] = wrow[g * 64 + 32 + l];
    }
    float bk_sel = (l < 4) ? wrow[256 + l] : 0.f;

    float ur0[TO], ur1[TO];
#pragma unroll
    for (int r = 0; r < TO; r++) {
        ur0[r] = uptr[r * 64 + l];
        ur1[r] = uptr[r * 64 + l + 32];
    }

#pragma unroll
    for (int r = 0; r < TO; r++) {
        float p0 = ur0[r] * wg0[0] + ur1[r] * wg1[0];
        float p1 = ur0[r] * wg0[1] + ur1[r] * wg1[1];
        float p2 = ur0[r] * wg0[2] + ur1[r] * wg1[2];
        float p3 = ur0[r] * wg0[3] + ur1[r] * wg1[3];
        float t0 = (l & 1) ? p0 : p1;
        float r0 = __shfl_xor_sync(FULLMASK, t0, 1);
        float a = ((l & 1) ? p1 : p0) + r0;
        float t1 = (l & 1) ? p2 : p3;
        float r1 = __shfl_xor_sync(FULLMASK, t1, 1);
        float bb = ((l & 1) ? p3 : p2) + r1;
        float t2 = (l & 2) ? a : bb;
        float r2 = __shfl_xor_sync(FULLMASK, t2, 2);
        float c = ((l & 2) ? bb : a) + r2;
        c += __shfl_xor_sync(FULLMASK, c, 4);
        c += __shfl_xor_sync(FULLMASK, c, 8);
        c += __shfl_xor_sync(FULLMASK, c, 16);
        if (l < 4) myLog[r * 4 + l] = c + bk_sel;
    }
    __syncwarp();

    if (l < 4) {
        float m = -1e30f;
#pragma unroll
        for (int r = 0; r < TO; r++) m = fmaxf(m, myLog[r * 4 + l]);
        float s = 0.f;
#pragma unroll
        for (int r = 0; r < TO; r++) {
            float e = __expf(myLog[r * 4 + l] - m);
            s += e;
            myLog[r * 4 + l] = e;
        }
        float inv = 1.f / s;
#pragma unroll
        for (int r = 0; r < TO; r++) myLog[r * 4 + l] *= inv;
    }
    __syncwarp();

    float ub0[4] = {0.f, 0.f, 0.f, 0.f}, ub1[4] = {0.f, 0.f, 0.f, 0.f};
#pragma unroll
    for (int r = 0; r < TO; r++) {
        float pg0 = myLog[r * 4 + 0], pg1 = myLog[r * 4 + 1];
        float pg2 = myLog[r * 4 + 2], pg3 = myLog[r * 4 + 3];
        ub0[0] += pg0 * ur0[r]; ub1[0] += pg0 * ur1[r];
        ub0[1] += pg1 * ur0[r]; ub1[1] += pg1 * ur1[r];
        ub0[2] += pg2 * ur0[r]; ub1[2] += pg2 * ur1[r];
        ub0[3] += pg3 * ur0[r]; ub1[3] += pg3 * ur1[r];
    }

#pragma unroll
    for (int g = 0; g < 4; g++) {
        wrow[g * 64 + l]      = to_tf32(ub0[g]);
        wrow[g * 64 + 32 + l] = to_tf32(ub1[g]);
    }
}

// ---------------------------------------------------------------------------
// Kernel A: per 32-token tile — u L2-prefetch, W-GEMM, warp attention,
// V-GEMM + LN1.  4 CTAs/SM.
// ---------------------------------------------------------------------------
extern "C" __global__ void __launch_bounds__(256, 4)
kernelA(const float* __restrict__ u, const float* __restrict__ x,
        const float* __restrict__ bv,
        const float* __restrict__ g1, const float* __restrict__ be1)
{
    extern __shared__ float sm[];
    float* sGC   = sm;              // 264
    float* sbv   = sGC + 264;       // 64
    float* sg1   = sbv + 64;        // 64
    float* sbe1  = sg1 + 64;        // 64
    float* sX    = sbe1 + 64;       // 32*68 = 2176
    float* sWt   = sX + 2176;       // 32*265 = 8480 (w-vectors, then ubar)
    float* sLog  = sWt + 8480;      // 8*64 = 512
    float* sRedS = sLog + 512;      // 128
    float* sRedQ = sRedS + 128;     // 128

    int tid = threadIdx.x;
    for (int i = tid; i < 264; i += 256) sGC[i] = gC[i];
    if (tid < 64) { sbv[tid] = bv[tid]; sg1[tid] = g1[tid]; sbe1[tid] = be1[tid]; }
    __syncthreads();

    const int warp = tid >> 5, l = tid & 31;
    const int wm = warp >> 2, wn = warp & 3;     // 2 m-tiles x 4 n-groups
    const int lq = l >> 2, lr = l & 3;
    float* myLog = sLog + warp * 64;

    for (int blk = blockIdx.x; blk < 1792; blk += gridDim.x) {
        int b = blk / 224;
        int n_base = (blk % 224) * 32;

        // ---- prefetch this tile's contiguous u region into L2 ----
        {
            int TOv, S0v, S1v, tv;
            if (n_base < 4096)      { TOv = 4;  tv = n_base;        S0v = 0;     S1v = 24576; }
            else if (n_base < 6144) { TOv = 8;  tv = n_base - 4096; S0v = 8192;  S1v = 32768; }
            else                    { TOv = 16; tv = n_base - 6144; S0v = 16384; S1v = 40960; }
            int cidx = tv * TOv;
            int ubase = (cidx < 8192) ? (S0v + cidx) : (S1v + cidx - 8192);
            const char* up = (const char*)(u + ((size_t)b * Uu + ubase) * Cc);
            int lines = 64 * TOv;                 // 32*TO rows * 256B / 128B
            for (int i = tid; i < lines; i += 256)
                asm volatile("prefetch.global.L2 [%0];" :: "l"(up + (size_t)i * 128));
        }

        {
            int row = tid >> 3, seg = (tid & 7) * 8;
            const float* xp = x + ((size_t)b * Nn + n_base + row) * 64 + seg;
            float4 a4 = *(const float4*)xp;
            float4 b4 = *(const float4*)(xp + 4);
            a4.x = to_tf32(a4.x); a4.y = to_tf32(a4.y); a4.z = to_tf32(a4.z); a4.w = to_tf32(a4.w);
            b4.x = to_tf32(b4.x); b4.y = to_tf32(b4.y); b4.z = to_tf32(b4.z); b4.w = to_tf32(b4.w);
            *(float4*)&sX[row * 68 + seg] = a4;
            *(float4*)&sX[row * 68 + seg + 4] = b4;
        }
        __syncthreads();

        // GEMM-W: Wt[32x264] = X @ gM (+gC)
        {
            float c[9][4];
#pragma unroll
            for (int nt = 0; nt < 9; nt++)
#pragma unroll
                for (int j = 0; j < 4; j++) c[nt][j] = 0.f;

            const float* A1 = sX + (wm * 16 + lq) * 68 + lr;
#pragma unroll
            for (int k0 = 0; k0 < 64; k0 += 8) {
                uint32_t a0 = __float_as_uint(A1[k0]);
                uint32_t a1 = __float_as_uint(A1[k0 + 8 * 68]);
                uint32_t a2 = __float_as_uint(A1[k0 + 4]);
                uint32_t a3 = __float_as_uint(A1[k0 + 8 * 68 + 4]);
                const float* Bp = gM + (k0 + lr) * 264 + lq;
#pragma unroll
                for (int nt = 0; nt < 8; nt++) {
                    int cb = wn * 64 + nt * 8;
                    uint32_t b0 = __float_as_uint(Bp[cb]);
                    uint32_t b1 = __float_as_uint(Bp[4 * 264 + cb]);
                    mma_tf32(c[nt], a0, a1, a2, a3, b0, b1);
                }
                if (wn == 0) {
                    uint32_t b0 = __float_as_uint(Bp[256]);
                    uint32_t b1 = __float_as_uint(Bp[4 * 264 + 256]);
                    mma_tf32(c[8], a0, a1, a2, a3, b0, b1);
                }
            }
            int r0 = wm * 16 + lq, r1 = r0 + 8;
#pragma unroll
            for (int nt = 0; nt < 8; nt++) {
                int col = wn * 64 + nt * 8 + lr * 2;
                sWt[r0 * 265 + col]     = c[nt][0] + sGC[col];
                sWt[r0 * 265 + col + 1] = c[nt][1] + sGC[col + 1];
                sWt[r1 * 265 + col]     = c[nt][2] + sGC[col];
                sWt[r1 * 265 + col + 1] = c[nt][3] + sGC[col + 1];
            }
            if (wn == 0) {
                int col = 256 + lr * 2;
                sWt[r0 * 265 + col]     = c[8][0] + sGC[col];
                sWt[r0 * 265 + col + 1] = c[8][1] + sGC[col + 1];
                sWt[r1 * 265 + col]     = c[8][2] + sGC[col];
                sWt[r1 * 265 + col + 1] = c[8][3] + sGC[col + 1];
            }
        }
        __syncthreads();

#pragma unroll
        for (int tt = 0; tt < 4; tt++) {
            int ltok = warp * 4 + tt;
            int n = n_base + ltok;
            if (n_base < 4096)
                attn_tok<4>(u, sWt, myLog, b, n, ltok, l);
            else if (n_base < 6144)
                attn_tok<8>(u, sWt, myLog, b, n, ltok, l);
            else
                attn_tok<16>(u, sWt, myLog, b, n, ltok, l);
        }
        __syncthreads();

        // V-GEMM: attv[32x64] = Ub[32x256] @ gWv (+bv); LN1 -> g_z1
        {
            float oA[2][4], oB[2][4];
#pragma unroll
            for (int nt = 0; nt < 2; nt++)
#pragma unroll
                for (int j = 0; j < 4; j++) { oA[nt][j] = 0.f; oB[nt][j] = 0.f; }

            const float* A = sWt + (wm * 16 + lq) * 265 + lr;
#pragma unroll
            for (int k0 = 0; k0 < 256; k0 += 16) {
                uint32_t a0 = __float_as_uint(A[k0]);
                uint32_t a1 = __float_as_uint(A[k0 + 8 * 265]);
                uint32_t a2 = __float_as_uint(A[k0 + 4]);
                uint32_t a3 = __float_as_uint(A[k0 + 8 * 265 + 4]);
                const float* Bp = gWv + (k0 + lr) * 72 + wn * 16 + lq;
#pragma unroll
                for (int nt = 0; nt < 2; nt++) {
                    uint32_t b0 = __float_as_uint(Bp[nt * 8]);
                    uint32_t b1 = __float_as_uint(Bp[4 * 72 + nt * 8]);
                    mma_tf32(oA[nt], a0, a1, a2, a3, b0, b1);
                }
                uint32_t c0 = __float_as_uint(A[k0 + 8]);
                uint32_t c1 = __float_as_uint(A[k0 + 8 + 8 * 265]);
                uint32_t c2 = __float_as_uint(A[k0 + 8 + 4]);
                uint32_t c3 = __float_as_uint(A[k0 + 8 + 8 * 265 + 4]);
                const float* Bq = gWv + (k0 + 8 + lr) * 72 + wn * 16 + lq;
#pragma unroll
                for (int nt = 0; nt < 2; nt++) {
                    uint32_t b0 = __float_as_uint(Bq[nt * 8]);
                    uint32_t b1 = __float_as_uint(Bq[4 * 72 + nt * 8]);
                    mma_tf32(oB[nt], c0, c1, c2, c3, b0, b1);
                }
            }
            float o[2][4];
#pragma unroll
            for (int nt = 0; nt < 2; nt++) {
                int col = wn * 16 + nt * 8 + lr * 2;
                o[nt][0] = oA[nt][0] + oB[nt][0] + sbv[col];
                o[nt][1] = oA[nt][1] + oB[nt][1] + sbv[col + 1];
                o[nt][2] = oA[nt][2] + oB[nt][2] + sbv[col];
                o[nt][3] = oA[nt][3] + oB[nt][3] + sbv[col + 1];
            }
            int r0 = wm * 16 + lq, r1 = r0 + 8;
            float slo = o[0][0] + o[0][1] + o[1][0] + o[1][1];
            float shi = o[0][2] + o[0][3] + o[1][2] + o[1][3];
            float qlo = o[0][0]*o[0][0] + o[0][1]*o[0][1] + o[1][0]*o[1][0] + o[1][1]*o[1][1];
            float qhi = o[0][2]*o[0][2] + o[0][3]*o[0][3] + o[1][2]*o[1][2] + o[1][3]*o[1][3];
#pragma unroll
            for (int off = 1; off <= 2; off <<= 1) {
                slo += __shfl_xor_sync(FULLMASK, slo, off);
                shi += __shfl_xor_sync(FULLMASK, shi, off);
                qlo += __shfl_xor_sync(FULLMASK, qlo, off);
                qhi += __shfl_xor_sync(FULLMASK, qhi, off);
            }
            if (lr == 0) {
                sRedS[r0 * 4 + wn] = slo;  sRedQ[r0 * 4 + wn] = qlo;
                sRedS[r1 * 4 + wn] = shi;  sRedQ[r1 * 4 + wn] = qhi;
            }
            __syncthreads();

            float msl = 0.f, mql = 0.f, msh = 0.f, mqh = 0.f;
#pragma unroll
            for (int j = 0; j < 4; j++) {
                msl += sRedS[r0 * 4 + j];  mql += sRedQ[r0 * 4 + j];
                msh += sRedS[r1 * 4 + j];  mqh += sRedQ[r1 * 4 + j];
            }
            float mean_lo = msl * (1.f / 64.f);
            float mean_hi = msh * (1.f / 64.f);
            float inv_lo = rsqrtf(mql * (1.f / 64.f) - mean_lo * mean_lo + 1e-5f);
            float inv_hi = rsqrtf(mqh * (1.f / 64.f) - mean_hi * mean_hi + 1e-5f);

            size_t gb = ((size_t)b * Nn + n_base) * 64;
#pragma unroll
            for (int nt = 0; nt < 2; nt++) {
                int col = wn * 16 + nt * 8 + lr * 2;
                float ga = sg1[col], gbq = sg1[col + 1];
                float ea = sbe1[col], eb = sbe1[col + 1];
                float2 rlo, rhi;
                rlo.x = (o[nt][0] - mean_lo) * inv_lo * ga  + ea;
                rlo.y = (o[nt][1] - mean_lo) * inv_lo * gbq + eb;
                rhi.x = (o[nt][2] - mean_hi) * inv_hi * ga  + ea;
                rhi.y = (o[nt][3] - mean_hi) * inv_hi * gbq + eb;
                *(float2*)(g_z1 + gb + (size_t)r0 * 64 + col) = rlo;
                *(float2*)(g_z1 + gb + (size_t)r1 * 64 + col) = rhi;
            }
        }
        __syncthreads();
    }
}

// ---------------------------------------------------------------------------
// Kernel B: MLP + LN2 + shortcut. GEMM2 B-fragments hoisted to registers;
// next-tile Z/X register-prefetched.  (unchanged from R12)
// ---------------------------------------------------------------------------
constexpr int P_WM1 = 264;
constexpr int P_WS  = 72;
constexpr int P_Z   = 68;
constexpr int P_H   = 260;

extern "C" __global__ void __launch_bounds__(512)
kernelB(const float* __restrict__ x,
        const float* __restrict__ Wm1, const float* __restrict__ bm1,
        const float* __restrict__ Wm2, const float* __restrict__ bm2,
        const float* __restrict__ g2,  const float* __restrict__ be2,
        const float* __restrict__ Ws,  const float* __restrict__ bs,
        float* __restrict__ out)
{
    extern __shared__ float sm[];
    float* sWm1f = sm;                    // 16896
    float* sWsf  = sWm1f + 64 * P_WM1;    // 4608
    float* sbm1  = sWsf + 64 * P_WS;      // 256
    float* sbm2  = sbm1 + 256;            // 64
    float* sg2   = sbm2 + 64;
    float* sbe2  = sg2 + 64;
    float* sbs   = sbe2 + 64;
    float* sZ    = sbs + 64;              // 2176
    float* sX    = sZ + 32 * P_Z;         // 2176
    float* sH    = sX + 32 * P_Z;         // 8320
    float* sRedS = sH + 32 * P_H;         // 256
    float* sRedQ = sRedS + 256;           // 256

    int tid = threadIdx.x;
    for (int i = tid; i < 64 * 256; i += 512) {
        int k = i >> 8, n = i & 255;
        sWm1f[k * P_WM1 + n] = to_tf32(Wm1[i]);
    }
    for (int i = tid; i < 64 * 64; i += 512) {
        int k = i >> 6, n = i & 63;
        sWsf[k * P_WS + n] = to_tf32(Ws[i]);
    }
    if (tid < 256) sbm1[tid] = bm1[tid];
    if (tid < 64) { sbm2[tid] = bm2[tid]; sg2[tid] = g2[tid]; sbe2[tid] = be2[tid]; sbs[tid] = bs[tid]; }

    const int warp = tid >> 5, lane = tid & 31;
    const int wm = warp >> 3, wn = warp & 7;
    const int lq = lane >> 2, lr = lane & 3;
    const int row_lo = wm * 16 + lq;
    const int row_hi = row_lo + 8;
    const int NTILES = Bb * Nn / 32;

    uint32_t B2r[64];
    {
        const float* p = Wm2 + wn * 8 + lq;
#pragma unroll
        for (int kidx = 0; kidx < 32; kidx++) {
            B2r[2 * kidx]     = __float_as_uint(to_tf32(p[(kidx * 8 + lr) * 64]));
            B2r[2 * kidx + 1] = __float_as_uint(to_tf32(p[(kidx * 8 + lr + 4) * 64]));
        }
    }
    __syncthreads();

    const int prow = tid >> 4, pseg = (tid & 15) * 4;

    float4 pz, px;
    {
        int blk = blockIdx.x;
        if (blk < NTILES) {
            size_t base = (size_t)blk * 2048;
            pz = *(const float4*)(g_z1 + base + prow * 64 + pseg);
            px = *(const float4*)(x + base + prow * 64 + pseg);
        }
    }

    for (int tile = blockIdx.x; tile < NTILES; tile += gridDim.x) {
        size_t base = (size_t)tile * 2048;
        {
            float4 z4 = pz, x4 = px;
            z4.x = to_tf32(z4.x); z4.y = to_tf32(z4.y); z4.z = to_tf32(z4.z); z4.w = to_tf32(z4.w);
            x4.x = to_tf32(x4.x); x4.y = to_tf32(x4.y); x4.z = to_tf32(x4.z); x4.w = to_tf32(x4.w);
            *(float4*)&sZ[prow * P_Z + pseg] = z4;
            *(float4*)&sX[prow * P_Z + pseg] = x4;
        }
        __syncthreads();

        float c[4][4];
#pragma unroll
        for (int nt = 0; nt < 4; nt++)
#pragma unroll
            for (int j = 0; j < 4; j++) c[nt][j] = 0.f;

        const float* A1 = sZ + row_lo * P_Z + lr;
#pragma unroll
        for (int k0 = 0; k0 < 64; k0 += 8) {
            uint32_t a0 = __float_as_uint(A1[k0]);
            uint32_t a1 = __float_as_uint(A1[k0 + 8 * P_Z]);
            uint32_t a2 = __float_as_uint(A1[k0 + 4]);
            uint32_t a3 = __float_as_uint(A1[k0 + 8 * P_Z + 4]);
            const float* B1 = sWm1f + (k0 + lr) * P_WM1 + wn * 32 + lq;
#pragma unroll
            for (int nt = 0; nt < 4; nt++) {
                uint32_t b0 = __float_as_uint(B1[nt * 8]);
                uint32_t b1 = __float_as_uint(B1[4 * P_WM1 + nt * 8]);
                mma_tf32(c[nt], a0, a1, a2, a3, b0, b1);
            }
        }
#pragma unroll
        for (int nt = 0; nt < 4; nt++) {
            int col = wn * 32 + nt * 8 + lr * 2;
            float v0 = c[nt][0] + sbm1[col];
            float v1 = c[nt][1] + sbm1[col + 1];
            float v2 = c[nt][2] + sbm1[col];
            float v3 = c[nt][3] + sbm1[col + 1];
            sH[row_lo * P_H + col]     = to_tf32(v0 * 0.5f * (1.f + erff(v0 * 0.70710678118654752f)));
            sH[row_lo * P_H + col + 1] = to_tf32(v1 * 0.5f * (1.f + erff(v1 * 0.70710678118654752f)));
            sH[row_hi * P_H + col]     = to_tf32(v2 * 0.5f * (1.f + erff(v2 * 0.70710678118654752f)));
            sH[row_hi * P_H + col + 1] = to_tf32(v3 * 0.5f * (1.f + erff(v3 * 0.70710678118654752f)));
        }
        __syncthreads();

        {
            int nblk = tile + gridDim.x;
            if (nblk < NTILES) {
                size_t nbase = (size_t)nblk * 2048;
                pz = *(const float4*)(g_z1 + nbase + prow * 64 + pseg);
                px = *(const float4*)(x + nbase + prow * 64 + pseg);
            }
        }

        float oE[4] = {0.f, 0.f, 0.f, 0.f};
        float oO[4] = {0.f, 0.f, 0.f, 0.f};
        float s[4] = {0.f, 0.f, 0.f, 0.f};
        const float* A2 = sH + row_lo * P_H + lr;
#pragma unroll
        for (int j = 0; j < 16; j++) {
            int kE = j * 16;
            {
                uint32_t a0 = __float_as_uint(A2[kE]);
                uint32_t a1 = __float_as_uint(A2[kE + 8 * P_H]);
                uint32_t a2 = __float_as_uint(A2[kE + 4]);
                uint32_t a3 = __float_as_uint(A2[kE + 8 * P_H + 4]);
                mma_tf32(oE, a0, a1, a2, a3, B2r[4 * j], B2r[4 * j + 1]);
            }
            {
                int kO = kE + 8;
                uint32_t a0 = __float_as_uint(A2[kO]);
                uint32_t a1 = __float_as_uint(A2[kO + 8 * P_H]);
                uint32_t a2 = __float_as_uint(A2[kO + 4]);
                uint32_t a3 = __float_as_uint(A2[kO + 8 * P_H + 4]);
                mma_tf32(oO, a0, a1, a2, a3, B2r[4 * j + 2], B2r[4 * j + 3]);
            }
        }
        const float* A3 = sX + row_lo * P_Z + lr;
        const float* B3 = sWsf + lr * P_WS + wn * 8 + lq;
#pragma unroll
        for (int k0 = 0; k0 < 64; k0 += 8) {
            uint32_t a0 = __float_as_uint(A3[k0]);
            uint32_t a1 = __float_as_uint(A3[k0 + 8 * P_Z]);
            uint32_t a2 = __float_as_uint(A3[k0 + 4]);
            uint32_t a3 = __float_as_uint(A3[k0 + 8 * P_Z + 4]);
            uint32_t b0 = __float_as_uint(B3[k0 * P_WS]);
            uint32_t b1 = __float_as_uint(B3[(k0 + 4) * P_WS]);
            mma_tf32(s, a0, a1, a2, a3, b0, b1);
        }

        int col = wn * 8 + lr * 2;
        float o[4];
        o[0] = oE[0] + oO[0] + sbm2[col];
        o[1] = oE[1] + oO[1] + sbm2[col + 1];
        o[2] = oE[2] + oO[2] + sbm2[col];
        o[3] = oE[3] + oO[3] + sbm2[col + 1];

        float slo = o[0] + o[1], shi = o[2] + o[3];
        float qlo = o[0] * o[0] + o[1] * o[1], qhi = o[2] * o[2] + o[3] * o[3];
#pragma unroll
        for (int off = 1; off <= 2; off <<= 1) {
            slo += __shfl_xor_sync(FULLMASK, slo, off);
            shi += __shfl_xor_sync(FULLMASK, shi, off);
            qlo += __shfl_xor_sync(FULLMASK, qlo, off);
            qhi += __shfl_xor_sync(FULLMASK, qhi, off);
        }
        if (lr == 0) {
            sRedS[row_lo * 8 + wn] = slo;  sRedQ[row_lo * 8 + wn] = qlo;
            sRedS[row_hi * 8 + wn] = shi;  sRedQ[row_hi * 8 + wn] = qhi;
        }
        __syncthreads();

        float ms_lo = 0.f, mq_lo = 0.f, ms_hi = 0.f, mq_hi = 0.f;
#pragma unroll
        for (int j = 0; j < 8; j++) {
            ms_lo += sRedS[row_lo * 8 + j];  mq_lo += sRedQ[row_lo * 8 + j];
            ms_hi += sRedS[row_hi * 8 + j];  mq_hi += sRedQ[row_hi * 8 + j];
        }
        float mean_lo = ms_lo * (1.f / 64.f);
        float mean_hi = ms_hi * (1.f / 64.f);
        float inv_lo = rsqrtf(mq_lo * (1.f / 64.f) - mean_lo * mean_lo + 1e-5f);
        float inv_hi = rsqrtf(mq_hi * (1.f / 64.f) - mean_hi * mean_hi + 1e-5f);

        float g0 = sg2[col], g1v = sg2[col + 1];
        float e0 = sbe2[col], e1 = sbe2[col + 1];
        float bs0 = sbs[col], bs1 = sbs[col + 1];

        float2 r_lo, r_hi;
        r_lo.x = (o[0] - mean_lo) * inv_lo * g0  + e0 + s[0] + bs0;
        r_lo.y = (o[1] - mean_lo) * inv_lo * g1v + e1 + s[1] + bs1;
        r_hi.x = (o[2] - mean_hi) * inv_hi * g0  + e0 + s[2] + bs0;
        r_hi.y = (o[3] - mean_hi) * inv_hi * g1v + e1 + s[3] + bs1;

        *(float2*)(out + base + (size_t)row_lo * 64 + col) = r_lo;
        *(float2*)(out + base + (size_t)row_hi * 64 + col) = r_hi;
        __syncthreads();
    }
}

// ---------------------------------------------------------------------------
extern "C" void kernel_launch(void* const* d_in, const int* in_sizes, int n_in,
                              void* d_out, int out_size)
{
    const float* u   = (const float*)d_in[0];
    const float* x   = (const float*)d_in[1];
    const float* Wk  = (const float*)d_in[2];
    const float* bk  = (const float*)d_in[3];
    const float* Wq  = (const float*)d_in[4];
    const float* bq  = (const float*)d_in[5];
    const float* Wv  = (const float*)d_in[6];
    const float* bv  = (const float*)d_in[7];
    const float* g1  = (const float*)d_in[8];
    const float* be1 = (const float*)d_in[9];
    const float* Wm1 = (const float*)d_in[10];
    const float* bm1 = (const float*)d_in[11];
    const float* Wm2 = (const float*)d_in[12];
    const float* bm2 = (const float*)d_in[13];
    const float* g2  = (const float*)d_in[14];
    const float* be2 = (const float*)d_in[15];
    const float* Ws  = (const float*)d_in[16];
    const float* bs  = (const float*)d_in[17];
    float* out = (float*)d_out;

    const int smemA = (264 + 3 * 64 + 2176 + 8480 + 512 + 256) * 4;   // 47520 B
    const int smemB = (16896 + 4608 + 256 + 4 * 64 + 2176 + 2176 + 8320 + 512) * 4; // 140,800 B

    cudaFuncSetAttribute(kernelA, cudaFuncAttributeMaxDynamicSharedMemorySize, smemA);
    cudaFuncSetAttribute(kernelB, cudaFuncAttributeMaxDynamicSharedMemorySize, smemB);

    kernelM<<<140, 256>>>(Wk, bk, Wq, bq, Wv);
    kernelA<<<592, 256, smemA>>>(u, x, bv, g1, be1);
    kernelB<<<148, 512, smemB>>>(x, Wm1, bm1, Wm2, bm2, g2, be2, Ws, bs, out);
}

// round 15
// speedup vs baseline: 1.0230x; 1.0230x over previous
#include <cuda_runtime.h>
#include <math.h>
#include <stdint.h>

#define FULLMASK 0xffffffffu

constexpr int Bb = 8;
constexpr int Nn = 7168;
constexpr int Uu = 49152;
constexpr int Cc = 64;

constexpr int P_WT = 266;   // sWt pitch (even -> float2-aligned rows)

// scratch buffers
__device__ float g_z1[Bb * Nn * Cc];     // post-LN1 attention output
__device__ float gM[64 * 264];           // folded W-projection matrix (tf32 values)
__device__ float gC[264];                // folded bias row
__device__ float gWv[256 * 72];          // block-diagonal V matrix (tf32), row=g*64+in

__device__ __forceinline__ float to_tf32(float x) {
    uint32_t r;
    asm("cvt.rna.tf32.f32 %0, %1;" : "=r"(r) : "f"(x));
    return __uint_as_float(r);
}

__device__ __forceinline__ void mma_tf32(float c[4],
    uint32_t a0, uint32_t a1, uint32_t a2, uint32_t a3,
    uint32_t b0, uint32_t b1)
{
    asm volatile(
        "mma.sync.aligned.m16n8k8.row.col.f32.tf32.tf32.f32 "
        "{%0,%1,%2,%3},{%4,%5,%6,%7},{%8,%9},{%0,%1,%2,%3};\n"
        : "+f"(c[0]), "+f"(c[1]), "+f"(c[2]), "+f"(c[3])
        : "r"(a0), "r"(a1), "r"(a2), "r"(a3), "r"(b0), "r"(b1));
}

// ---------------------------------------------------------------------------
// Kernel M: fold Wq/Wk/bq/bk (+scale) into gM/gC; build block-diagonal gWv
// ---------------------------------------------------------------------------
extern "C" __global__ void kernelM(
    const float* __restrict__ Wk, const float* __restrict__ bk,
    const float* __restrict__ Wq, const float* __restrict__ bq,
    const float* __restrict__ Wv)
{
    int idx = blockIdx.x * 256 + threadIdx.x;
    if (idx < 64 * 264) {
        int j = idx / 264, col = idx % 264;
        float acc = 0.f;
        if (col < 256) {
            int g = col >> 6, in = col & 63;
#pragma unroll
            for (int oo = 0; oo < 16; oo++) {
                int oc = g * 16 + oo;
                acc += Wq[j * 64 + oc] * Wk[in * 64 + oc];
            }
        } else if (col < 260) {
            int g = col - 256;
#pragma unroll
            for (int oo = 0; oo < 16; oo++) {
                int oc = g * 16 + oo;
                acc += Wq[j * 64 + oc] * bk[oc];
            }
        }
        gM[idx] = to_tf32(0.125f * acc);
    } else if (idx < 64 * 264 + 264) {
        int col = idx - 64 * 264;
        float acc = 0.f;
        if (col < 256) {
            int g = col >> 6, in = col & 63;
#pragma unroll
            for (int oo = 0; oo < 16; oo++) {
                int oc = g * 16 + oo;
                acc += bq[oc] * Wk[in * 64 + oc];
            }
        } else if (col < 260) {
            int g = col - 256;
#pragma unroll
            for (int oo = 0; oo < 16; oo++) {
                int oc = g * 16 + oo;
                acc += bq[oc] * bk[oc];
            }
        }
        gC[col] = 0.125f * acc;
    } else if (idx < 64 * 264 + 264 + 256 * 72) {
        int j = idx - (64 * 264 + 264);
        int row = j / 72, oc = j % 72;
        float v = 0.f;
        if (oc < 64) {
            int g = row >> 6, in = row & 63;
            if ((oc >> 4) == g) v = Wv[in * 64 + oc];
        }
        gWv[row * 72 + oc] = to_tf32(v);
    }
}

// ---------------------------------------------------------------------------
// Kernel A attention epilogue for one token (channel-pair layout):
// lane l owns channels 2l, 2l+1.  logits/softmax/ubar -> sWt row (tf32).
// ---------------------------------------------------------------------------
template <int TO>
__device__ __forceinline__ void attn_tok(
    const float* __restrict__ u,
    float* sWt, float* myLog, int b, int n, int ltok, int l)
{
    int t, S0, S1;
    if (TO == 4)      { t = n;        S0 = 0;     S1 = 24576; }
    else if (TO == 8) { t = n - 4096; S0 = 8192;  S1 = 32768; }
    else              { t = n - 6144; S0 = 16384; S1 = 40960; }
    int cidx = t * TO;
    int base = (cidx < 8192) ? (S0 + cidx) : (S1 + cidx - 8192);
    const float* uptr = u + ((size_t)b * Uu + base) * Cc;

    float* wrow = sWt + ltok * P_WT;
    // w vectors: lane's channel pair per group (float2 LDS)
    float2 wg[4];
#pragma unroll
    for (int g = 0; g < 4; g++)
        wg[g] = *(const float2*)&wrow[g * 64 + 2 * l];
    float bk_sel = (l < 4) ? wrow[256 + l] : 0.f;

    // load TO rows, one LDG.64 per row (channels 2l, 2l+1)
    float2 ur[TO];
#pragma unroll
    for (int r = 0; r < TO; r++)
        ur[r] = *(const float2*)(uptr + r * 64 + 2 * l);

    // logits: 6-shfl multi-value reduction
#pragma unroll
    for (int r = 0; r < TO; r++) {
        float p0 = ur[r].x * wg[0].x + ur[r].y * wg[0].y;
        float p1 = ur[r].x * wg[1].x + ur[r].y * wg[1].y;
        float p2 = ur[r].x * wg[2].x + ur[r].y * wg[2].y;
        float p3 = ur[r].x * wg[3].x + ur[r].y * wg[3].y;
        float t0 = (l & 1) ? p0 : p1;
        float r0 = __shfl_xor_sync(FULLMASK, t0, 1);
        float a = ((l & 1) ? p1 : p0) + r0;
        float t1 = (l & 1) ? p2 : p3;
        float r1 = __shfl_xor_sync(FULLMASK, t1, 1);
        float bb = ((l & 1) ? p3 : p2) + r1;
        float t2 = (l & 2) ? a : bb;
        float r2 = __shfl_xor_sync(FULLMASK, t2, 2);
        float c = ((l & 2) ? bb : a) + r2;
        c += __shfl_xor_sync(FULLMASK, c, 4);
        c += __shfl_xor_sync(FULLMASK, c, 8);
        c += __shfl_xor_sync(FULLMASK, c, 16);
        if (l < 4) myLog[r * 4 + l] = c + bk_sel;
    }
    __syncwarp();

    // softmax over r, one group per lane (lanes 0..3)
    if (l < 4) {
        float m = -1e30f;
#pragma unroll
        for (int r = 0; r < TO; r++) m = fmaxf(m, myLog[r * 4 + l]);
        float s = 0.f;
#pragma unroll
        for (int r = 0; r < TO; r++) {
            float e = __expf(myLog[r * 4 + l] - m);
            s += e;
            myLog[r * 4 + l] = e;
        }
        float inv = 1.f / s;
#pragma unroll
        for (int r = 0; r < TO; r++) myLog[r * 4 + l] *= inv;
    }
    __syncwarp();

    // ubar[g] over the lane's channel pair
    float2 ub[4];
#pragma unroll
    for (int g = 0; g < 4; g++) { ub[g].x = 0.f; ub[g].y = 0.f; }
#pragma unroll
    for (int r = 0; r < TO; r++) {
        float pg0 = myLog[r * 4 + 0], pg1 = myLog[r * 4 + 1];
        float pg2 = myLog[r * 4 + 2], pg3 = myLog[r * 4 + 3];
        ub[0].x += pg0 * ur[r].x; ub[0].y += pg0 * ur[r].y;
        ub[1].x += pg1 * ur[r].x; ub[1].y += pg1 * ur[r].y;
        ub[2].x += pg2 * ur[r].x; ub[2].y += pg2 * ur[r].y;
        ub[3].x += pg3 * ur[r].x; ub[3].y += pg3 * ur[r].y;
    }

    // overwrite this token's sWt row with tf32 ubar (float2 STS per group)
#pragma unroll
    for (int g = 0; g < 4; g++) {
        float2 v;
        v.x = to_tf32(ub[g].x);
        v.y = to_tf32(ub[g].y);
        *(float2*)&wrow[g * 64 + 2 * l] = v;
    }
}

// ---------------------------------------------------------------------------
// Kernel A: per 32-token tile — W-GEMM, warp attention, V-GEMM + LN1
// 4 CTAs/SM.
// ---------------------------------------------------------------------------
extern "C" __global__ void __launch_bounds__(256, 4)
kernelA(const float* __restrict__ u, const float* __restrict__ x,
        const float* __restrict__ bv,
        const float* __restrict__ g1, const float* __restrict__ be1)
{
    extern __shared__ float sm[];
    float* sGC   = sm;              // 264
    float* sbv   = sGC + 264;       // 64
    float* sg1   = sbv + 64;        // 64
    float* sbe1  = sg1 + 64;        // 64
    float* sX    = sbe1 + 64;       // 32*68 = 2176   (base offset 2632, even)
    float* sWt   = sX + 2176;       // 32*266 = 8512
    float* sLog  = sWt + 8512;      // 8*64 = 512
    float* sRedS = sLog + 512;      // 128
    float* sRedQ = sRedS + 128;     // 128

    int tid = threadIdx.x;
    for (int i = tid; i < 264; i += 256) sGC[i] = gC[i];
    if (tid < 64) { sbv[tid] = bv[tid]; sg1[tid] = g1[tid]; sbe1[tid] = be1[tid]; }
    __syncthreads();

    const int warp = tid >> 5, l = tid & 31;
    const int wm = warp >> 2, wn = warp & 3;     // 2 m-tiles x 4 n-groups
    const int lq = l >> 2, lr = l & 3;
    float* myLog = sLog + warp * 64;

    for (int blk = blockIdx.x; blk < 1792; blk += gridDim.x) {
        int b = blk / 224;
        int n_base = (blk % 224) * 32;

        {
            int row = tid >> 3, seg = (tid & 7) * 8;
            const float* xp = x + ((size_t)b * Nn + n_base + row) * 64 + seg;
            float4 a4 = *(const float4*)xp;
            float4 b4 = *(const float4*)(xp + 4);
            a4.x = to_tf32(a4.x); a4.y = to_tf32(a4.y); a4.z = to_tf32(a4.z); a4.w = to_tf32(a4.w);
            b4.x = to_tf32(b4.x); b4.y = to_tf32(b4.y); b4.z = to_tf32(b4.z); b4.w = to_tf32(b4.w);
            *(float4*)&sX[row * 68 + seg] = a4;
            *(float4*)&sX[row * 68 + seg + 4] = b4;
        }
        __syncthreads();

        // GEMM-W: Wt[32x264] = X @ gM (+gC)
        {
            float c[9][4];
#pragma unroll
            for (int nt = 0; nt < 9; nt++)
#pragma unroll
                for (int j = 0; j < 4; j++) c[nt][j] = 0.f;

            const float* A1 = sX + (wm * 16 + lq) * 68 + lr;
#pragma unroll
            for (int k0 = 0; k0 < 64; k0 += 8) {
                uint32_t a0 = __float_as_uint(A1[k0]);
                uint32_t a1 = __float_as_uint(A1[k0 + 8 * 68]);
                uint32_t a2 = __float_as_uint(A1[k0 + 4]);
                uint32_t a3 = __float_as_uint(A1[k0 + 8 * 68 + 4]);
                const float* Bp = gM + (k0 + lr) * 264 + lq;
#pragma unroll
                for (int nt = 0; nt < 8; nt++) {
                    int cb = wn * 64 + nt * 8;
                    uint32_t b0 = __float_as_uint(Bp[cb]);
                    uint32_t b1 = __float_as_uint(Bp[4 * 264 + cb]);
                    mma_tf32(c[nt], a0, a1, a2, a3, b0, b1);
                }
                if (wn == 0) {
                    uint32_t b0 = __float_as_uint(Bp[256]);
                    uint32_t b1 = __float_as_uint(Bp[4 * 264 + 256]);
                    mma_tf32(c[8], a0, a1, a2, a3, b0, b1);
                }
            }
            int r0 = wm * 16 + lq, r1 = r0 + 8;
#pragma unroll
            for (int nt = 0; nt < 8; nt++) {
                int col = wn * 64 + nt * 8 + lr * 2;
                sWt[r0 * P_WT + col]     = c[nt][0] + sGC[col];
                sWt[r0 * P_WT + col + 1] = c[nt][1] + sGC[col + 1];
                sWt[r1 * P_WT + col]     = c[nt][2] + sGC[col];
                sWt[r1 * P_WT + col + 1] = c[nt][3] + sGC[col + 1];
            }
            if (wn == 0) {
                int col = 256 + lr * 2;
                sWt[r0 * P_WT + col]     = c[8][0] + sGC[col];
                sWt[r0 * P_WT + col + 1] = c[8][1] + sGC[col + 1];
                sWt[r1 * P_WT + col]     = c[8][2] + sGC[col];
                sWt[r1 * P_WT + col + 1] = c[8][3] + sGC[col + 1];
            }
        }
        __syncthreads();

#pragma unroll
        for (int tt = 0; tt < 4; tt++) {
            int ltok = warp * 4 + tt;
            int n = n_base + ltok;
            if (n_base < 4096)
                attn_tok<4>(u, sWt, myLog, b, n, ltok, l);
            else if (n_base < 6144)
                attn_tok<8>(u, sWt, myLog, b, n, ltok, l);
            else
                attn_tok<16>(u, sWt, myLog, b, n, ltok, l);
        }
        __syncthreads();

        // V-GEMM: attv[32x64] = Ub[32x256] @ gWv (+bv); LN1 -> g_z1
        {
            float oA[2][4], oB[2][4];
#pragma unroll
            for (int nt = 0; nt < 2; nt++)
#pragma unroll
                for (int j = 0; j < 4; j++) { oA[nt][j] = 0.f; oB[nt][j] = 0.f; }

            const float* A = sWt + (wm * 16 + lq) * P_WT + lr;
#pragma unroll
            for (int k0 = 0; k0 < 256; k0 += 16) {
                uint32_t a0 = __float_as_uint(A[k0]);
                uint32_t a1 = __float_as_uint(A[k0 + 8 * P_WT]);
                uint32_t a2 = __float_as_uint(A[k0 + 4]);
                uint32_t a3 = __float_as_uint(A[k0 + 8 * P_WT + 4]);
                const float* Bp = gWv + (k0 + lr) * 72 + wn * 16 + lq;
#pragma unroll
                for (int nt = 0; nt < 2; nt++) {
                    uint32_t b0 = __float_as_uint(Bp[nt * 8]);
                    uint32_t b1 = __float_as_uint(Bp[4 * 72 + nt * 8]);
                    mma_tf32(oA[nt], a0, a1, a2, a3, b0, b1);
                }
                uint32_t c0 = __float_as_uint(A[k0 + 8]);
                uint32_t c1 = __float_as_uint(A[k0 + 8 + 8 * P_WT]);
                uint32_t c2 = __float_as_uint(A[k0 + 8 + 4]);
                uint32_t c3 = __float_as_uint(A[k0 + 8 + 8 * P_WT + 4]);
                const float* Bq = gWv + (k0 + 8 + lr) * 72 + wn * 16 + lq;
#pragma unroll
                for (int nt = 0; nt < 2; nt++) {
                    uint32_t b0 = __float_as_uint(Bq[nt * 8]);
                    uint32_t b1 = __float_as_uint(Bq[4 * 72 + nt * 8]);
                    mma_tf32(oB[nt], c0, c1, c2, c3, b0, b1);
                }
            }
            float o[2][4];
#pragma unroll
            for (int nt = 0; nt < 2; nt++) {
                int col = wn * 16 + nt * 8 + lr * 2;
                o[nt][0] = oA[nt][0] + oB[nt][0] + sbv[col];
                o[nt][1] = oA[nt][1] + oB[nt][1] + sbv[col + 1];
                o[nt][2] = oA[nt][2] + oB[nt][2] + sbv[col];
                o[nt][3] = oA[nt][3] + oB[nt][3] + sbv[col + 1];
            }
            int r0 = wm * 16 + lq, r1 = r0 + 8;
            float slo = o[0][0] + o[0][1] + o[1][0] + o[1][1];
            float shi = o[0][2] + o[0][3] + o[1][2] + o[1][3];
            float qlo = o[0][0]*o[0][0] + o[0][1]*o[0][1] + o[1][0]*o[1][0] + o[1][1]*o[1][1];
            float qhi = o[0][2]*o[0][2] + o[0][3]*o[0][3] + o[1][2]*o[1][2] + o[1][3]*o[1][3];
#pragma unroll
            for (int off = 1; off <= 2; off <<= 1) {
                slo += __shfl_xor_sync(FULLMASK, slo, off);
                shi += __shfl_xor_sync(FULLMASK, shi, off);
                qlo += __shfl_xor_sync(FULLMASK, qlo, off);
                qhi += __shfl_xor_sync(FULLMASK, qhi, off);
            }
            if (lr == 0) {
                sRedS[r0 * 4 + wn] = slo;  sRedQ[r0 * 4 + wn] = qlo;
                sRedS[r1 * 4 + wn] = shi;  sRedQ[r1 * 4 + wn] = qhi;
            }
            __syncthreads();

            float msl = 0.f, mql = 0.f, msh = 0.f, mqh = 0.f;
#pragma unroll
            for (int j = 0; j < 4; j++) {
                msl += sRedS[r0 * 4 + j];  mql += sRedQ[r0 * 4 + j];
                msh += sRedS[r1 * 4 + j];  mqh += sRedQ[r1 * 4 + j];
            }
            float mean_lo = msl * (1.f / 64.f);
            float mean_hi = msh * (1.f / 64.f);
            float inv_lo = rsqrtf(mql * (1.f / 64.f) - mean_lo * mean_lo + 1e-5f);
            float inv_hi = rsqrtf(mqh * (1.f / 64.f) - mean_hi * mean_hi + 1e-5f);

            size_t gb = ((size_t)b * Nn + n_base) * 64;
#pragma unroll
            for (int nt = 0; nt < 2; nt++) {
                int col = wn * 16 + nt * 8 + lr * 2;
                float ga = sg1[col], gbq = sg1[col + 1];
                float ea = sbe1[col], eb = sbe1[col + 1];
                float2 rlo, rhi;
                rlo.x = (o[nt][0] - mean_lo) * inv_lo * ga  + ea;
                rlo.y = (o[nt][1] - mean_lo) * inv_lo * gbq + eb;
                rhi.x = (o[nt][2] - mean_hi) * inv_hi * ga  + ea;
                rhi.y = (o[nt][3] - mean_hi) * inv_hi * gbq + eb;
                *(float2*)(g_z1 + gb + (size_t)r0 * 64 + col) = rlo;
                *(float2*)(g_z1 + gb + (size_t)r1 * 64 + col) = rhi;
            }
        }
        __syncthreads();
    }
}

// ---------------------------------------------------------------------------
// Kernel B: MLP + LN2 + shortcut. GEMM2 B-fragments hoisted to registers;
// next-tile Z/X register-prefetched.  (unchanged from R12)
// ---------------------------------------------------------------------------
constexpr int P_WM1 = 264;
constexpr int P_WS  = 72;
constexpr int P_Z   = 68;
constexpr int P_H   = 260;

extern "C" __global__ void __launch_bounds__(512)
kernelB(const float* __restrict__ x,
        const float* __restrict__ Wm1, const float* __restrict__ bm1,
        const float* __restrict__ Wm2, const float* __restrict__ bm2,
        const float* __restrict__ g2,  const float* __restrict__ be2,
        const float* __restrict__ Ws,  const float* __restrict__ bs,
        float* __restrict__ out)
{
    extern __shared__ float sm[];
    float* sWm1f = sm;                    // 16896
    float* sWsf  = sWm1f + 64 * P_WM1;    // 4608
    float* sbm1  = sWsf + 64 * P_WS;      // 256
    float* sbm2  = sbm1 + 256;            // 64
    float* sg2   = sbm2 + 64;
    float* sbe2  = sg2 + 64;
    float* sbs   = sbe2 + 64;
    float* sZ    = sbs + 64;              // 2176
    float* sX    = sZ + 32 * P_Z;         // 2176
    float* sH    = sX + 32 * P_Z;         // 8320
    float* sRedS = sH + 32 * P_H;         // 256
    float* sRedQ = sRedS + 256;           // 256

    int tid = threadIdx.x;
    for (int i = tid; i < 64 * 256; i += 512) {
        int k = i >> 8, n = i & 255;
        sWm1f[k * P_WM1 + n] = to_tf32(Wm1[i]);
    }
    for (int i = tid; i < 64 * 64; i += 512) {
        int k = i >> 6, n = i & 63;
        sWsf[k * P_WS + n] = to_tf32(Ws[i]);
    }
    if (tid < 256) sbm1[tid] = bm1[tid];
    if (tid < 64) { sbm2[tid] = bm2[tid]; sg2[tid] = g2[tid]; sbe2[tid] = be2[tid]; sbs[tid] = bs[tid]; }

    const int warp = tid >> 5, lane = tid & 31;
    const int wm = warp >> 3, wn = warp & 7;
    const int lq = lane >> 2, lr = lane & 3;
    const int row_lo = wm * 16 + lq;
    const int row_hi = row_lo + 8;
    const int NTILES = Bb * Nn / 32;

    uint32_t B2r[64];
    {
        const float* p = Wm2 + wn * 8 + lq;
#pragma unroll
        for (int kidx = 0; kidx < 32; kidx++) {
            B2r[2 * kidx]     = __float_as_uint(to_tf32(p[(kidx * 8 + lr) * 64]));
            B2r[2 * kidx + 1] = __float_as_uint(to_tf32(p[(kidx * 8 + lr + 4) * 64]));
        }
    }
    __syncthreads();

    const int prow = tid >> 4, pseg = (tid & 15) * 4;

    float4 pz, px;
    {
        int blk = blockIdx.x;
        if (blk < NTILES) {
            size_t base = (size_t)blk * 2048;
            pz = *(const float4*)(g_z1 + base + prow * 64 + pseg);
            px = *(const float4*)(x + base + prow * 64 + pseg);
        }
    }

    for (int tile = blockIdx.x; tile < NTILES; tile += gridDim.x) {
        size_t base = (size_t)tile * 2048;
        {
            float4 z4 = pz, x4 = px;
            z4.x = to_tf32(z4.x); z4.y = to_tf32(z4.y); z4.z = to_tf32(z4.z); z4.w = to_tf32(z4.w);
            x4.x = to_tf32(x4.x); x4.y = to_tf32(x4.y); x4.z = to_tf32(x4.z); x4.w = to_tf32(x4.w);
            *(float4*)&sZ[prow * P_Z + pseg] = z4;
            *(float4*)&sX[prow * P_Z + pseg] = x4;
        }
        __syncthreads();

        float c[4][4];
#pragma unroll
        for (int nt = 0; nt < 4; nt++)
#pragma unroll
            for (int j = 0; j < 4; j++) c[nt][j] = 0.f;

        const float* A1 = sZ + row_lo * P_Z + lr;
#pragma unroll
        for (int k0 = 0; k0 < 64; k0 += 8) {
            uint32_t a0 = __float_as_uint(A1[k0]);
            uint32_t a1 = __float_as_uint(A1[k0 + 8 * P_Z]);
            uint32_t a2 = __float_as_uint(A1[k0 + 4]);
            uint32_t a3 = __float_as_uint(A1[k0 + 8 * P_Z + 4]);
            const float* B1 = sWm1f + (k0 + lr) * P_WM1 + wn * 32 + lq;
#pragma unroll
            for (int nt = 0; nt < 4; nt++) {
                uint32_t b0 = __float_as_uint(B1[nt * 8]);
                uint32_t b1 = __float_as_uint(B1[4 * P_WM1 + nt * 8]);
                mma_tf32(c[nt], a0, a1, a2, a3, b0, b1);
            }
        }
#pragma unroll
        for (int nt = 0; nt < 4; nt++) {
            int col = wn * 32 + nt * 8 + lr * 2;
            float v0 = c[nt][0] + sbm1[col];
            float v1 = c[nt][1] + sbm1[col + 1];
            float v2 = c[nt][2] + sbm1[col];
            float v3 = c[nt][3] + sbm1[col + 1];
            sH[row_lo * P_H + col]     = to_tf32(v0 * 0.5f * (1.f + erff(v0 * 0.70710678118654752f)));
            sH[row_lo * P_H + col + 1] = to_tf32(v1 * 0.5f * (1.f + erff(v1 * 0.70710678118654752f)));
            sH[row_hi * P_H + col]     = to_tf32(v2 * 0.5f * (1.f + erff(v2 * 0.70710678118654752f)));
            sH[row_hi * P_H + col + 1] = to_tf32(v3 * 0.5f * (1.f + erff(v3 * 0.70710678118654752f)));
        }
        __syncthreads();

        {
            int nblk = tile + gridDim.x;
            if (nblk < NTILES) {
                size_t nbase = (size_t)nblk * 2048;
                pz = *(const float4*)(g_z1 + nbase + prow * 64 + pseg);
                px = *(const float4*)(x + nbase + prow * 64 + pseg);
            }
        }

        float oE[4] = {0.f, 0.f, 0.f, 0.f};
        float oO[4] = {0.f, 0.f, 0.f, 0.f};
        float s[4] = {0.f, 0.f, 0.f, 0.f};
        const float* A2 = sH + row_lo * P_H + lr;
#pragma unroll
        for (int j = 0; j < 16; j++) {
            int kE = j * 16;
            {
                uint32_t a0 = __float_as_uint(A2[kE]);
                uint32_t a1 = __float_as_uint(A2[kE + 8 * P_H]);
                uint32_t a2 = __float_as_uint(A2[kE + 4]);
                uint32_t a3 = __float_as_uint(A2[kE + 8 * P_H + 4]);
                mma_tf32(oE, a0, a1, a2, a3, B2r[4 * j], B2r[4 * j + 1]);
            }
            {
                int kO = kE + 8;
                uint32_t a0 = __float_as_uint(A2[kO]);
                uint32_t a1 = __float_as_uint(A2[kO + 8 * P_H]);
                uint32_t a2 = __float_as_uint(A2[kO + 4]);
                uint32_t a3 = __float_as_uint(A2[kO + 8 * P_H + 4]);
                mma_tf32(oO, a0, a1, a2, a3, B2r[4 * j + 2], B2r[4 * j + 3]);
            }
        }
        const float* A3 = sX + row_lo * P_Z + lr;
        const float* B3 = sWsf + lr * P_WS + wn * 8 + lq;
#pragma unroll
        for (int k0 = 0; k0 < 64; k0 += 8) {
            uint32_t a0 = __float_as_uint(A3[k0]);
            uint32_t a1 = __float_as_uint(A3[k0 + 8 * P_Z]);
            uint32_t a2 = __float_as_uint(A3[k0 + 4]);
            uint32_t a3 = __float_as_uint(A3[k0 + 8 * P_Z + 4]);
            uint32_t b0 = __float_as_uint(B3[k0 * P_WS]);
            uint32_t b1 = __float_as_uint(B3[(k0 + 4) * P_WS]);
            mma_tf32(s, a0, a1, a2, a3, b0, b1);
        }

        int col = wn * 8 + lr * 2;
        float o[4];
        o[0] = oE[0] + oO[0] + sbm2[col];
        o[1] = oE[1] + oO[1] + sbm2[col + 1];
        o[2] = oE[2] + oO[2] + sbm2[col];
        o[3] = oE[3] + oO[3] + sbm2[col + 1];

        float slo = o[0] + o[1], shi = o[2] + o[3];
        float qlo = o[0] * o[0] + o[1] * o[1], qhi = o[2] * o[2] + o[3] * o[3];
#pragma unroll
        for (int off = 1; off <= 2; off <<= 1) {
            slo += __shfl_xor_sync(FULLMASK, slo, off);
            shi += __shfl_xor_sync(FULLMASK, shi, off);
            qlo += __shfl_xor_sync(FULLMASK, qlo, off);
            qhi += __shfl_xor_sync(FULLMASK, qhi, off);
        }
        if (lr == 0) {
            sRedS[row_lo * 8 + wn] = slo;  sRedQ[row_lo * 8 + wn] = qlo;
            sRedS[row_hi * 8 + wn] = shi;  sRedQ[row_hi * 8 + wn] = qhi;
        }
        __syncthreads();

        float ms_lo = 0.f, mq_lo = 0.f, ms_hi = 0.f, mq_hi = 0.f;
#pragma unroll
        for (int j = 0; j < 8; j++) {
            ms_lo += sRedS[row_lo * 8 + j];  mq_lo += sRedQ[row_lo * 8 + j];
            ms_hi += sRedS[row_hi * 8 + j];  mq_hi += sRedQ[row_hi * 8 + j];
        }
        float mean_lo = ms_lo * (1.f / 64.f);
        float mean_hi = ms_hi * (1.f / 64.f);
        float inv_lo = rsqrtf(mq_lo * (1.f / 64.f) - mean_lo * mean_lo + 1e-5f);
        float inv_hi = rsqrtf(mq_hi * (1.f / 64.f) - mean_hi * mean_hi + 1e-5f);

        float g0 = sg2[col], g1v = sg2[col + 1];
        float e0 = sbe2[col], e1 = sbe2[col + 1];
        float bs0 = sbs[col], bs1 = sbs[col + 1];

        float2 r_lo, r_hi;
        r_lo.x = (o[0] - mean_lo) * inv_lo * g0  + e0 + s[0] + bs0;
        r_lo.y = (o[1] - mean_lo) * inv_lo * g1v + e1 + s[1] + bs1;
        r_hi.x = (o[2] - mean_hi) * inv_hi * g0  + e0 + s[2] + bs0;
        r_hi.y = (o[3] - mean_hi) * inv_hi * g1v + e1 + s[3] + bs1;

        *(float2*)(out + base + (size_t)row_lo * 64 + col) = r_lo;
        *(float2*)(out + base + (size_t)row_hi * 64 + col) = r_hi;
        __syncthreads();
    }
}

// ---------------------------------------------------------------------------
extern "C" void kernel_launch(void* const* d_in, const int* in_sizes, int n_in,
                              void* d_out, int out_size)
{
    const float* u   = (const float*)d_in[0];
    const float* x   = (const float*)d_in[1];
    const float* Wk  = (const float*)d_in[2];
    const float* bk  = (const float*)d_in[3];
    const float* Wq  = (const float*)d_in[4];
    const float* bq  = (const float*)d_in[5];
    const float* Wv  = (const float*)d_in[6];
    const float* bv  = (const float*)d_in[7];
    const float* g1  = (const float*)d_in[8];
    const float* be1 = (const float*)d_in[9];
    const float* Wm1 = (const float*)d_in[10];
    const float* bm1 = (const float*)d_in[11];
    const float* Wm2 = (const float*)d_in[12];
    const float* bm2 = (const float*)d_in[13];
    const float* g2  = (const float*)d_in[14];
    const float* be2 = (const float*)d_in[15];
    const float* Ws  = (const float*)d_in[16];
    const float* bs  = (const float*)d_in[17];
    float* out = (float*)d_out;

    const int smemA = (264 + 3 * 64 + 2176 + 32 * P_WT + 512 + 256) * 4;   // 47648 B
    const int smemB = (16896 + 4608 + 256 + 4 * 64 + 2176 + 2176 + 8320 + 512) * 4; // 140,800 B

    cudaFuncSetAttribute(kernelA, cudaFuncAttributeMaxDynamicSharedMemorySize, smemA);
    cudaFuncSetAttribute(kernelB, cudaFuncAttributeMaxDynamicSharedMemorySize, smemB);

    kernelM<<<140, 256>>>(Wk, bk, Wq, bq, Wv);
    kernelA<<<592, 256, smemA>>>(u, x, bv, g1, be1);
    kernelB<<<148, 512, smemB>>>(x, Wm1, bm1, Wm2, bm2, g2, be2, Ws, bs, out);
}